// round 1
// baseline (speedup 1.0000x reference)
#include <cuda_runtime.h>
#include <cstdint>

#define NB 256
#define NS 2048
#define NK 64

// Scratch (device globals — no allocation allowed)
__device__ float g_vecA[NB][NK];
__device__ float g_vecB[NB][NK];
__device__ float g_offA[NB];
__device__ float g_offB[NB];
__device__ float g_gold[NB];

typedef unsigned long long u64;

__device__ __forceinline__ u64 fma2(u64 a, u64 b, u64 c) {
    u64 d; asm("fma.rn.f32x2 %0, %1, %2, %3;" : "=l"(d) : "l"(a), "l"(b), "l"(c)); return d;
}
__device__ __forceinline__ u64 add2(u64 a, u64 b) {
    u64 d; asm("add.rn.f32x2 %0, %1, %2;" : "=l"(d) : "l"(a), "l"(b)); return d;
}
__device__ __forceinline__ u64 pack2(float x, float y) {
    u64 d; asm("mov.b64 %0, {%1, %2};" : "=l"(d) : "f"(x), "f"(y)); return d;
}
__device__ __forceinline__ float2 unpack2(u64 v) {
    float2 f; asm("mov.b64 {%0, %1}, %2;" : "=f"(f.x), "=f"(f.y) : "l"(v)); return f;
}

// One warp = one half-chain (forward or backward) of one batch element.
// E (exp of transition) lives in 128 registers per lane (column-pair for fwd,
// row-pair for bwd). The broadcast vector lives in shared as duplicated pairs:
// sh[i] = (v[i], v[i]) so a single LDS.128 broadcast feeds two fma.f32x2.
__global__ void __launch_bounds__(128, 1)
crf_chains(const float* __restrict__ scores, const float* __restrict__ trans,
           const float* __restrict__ source, const float* __restrict__ sink)
{
    __shared__ u64 sh[4][2][NK];   // [warp][double-buffer][dup-pair]

    const int w = threadIdx.x >> 5;
    const int l = threadIdx.x & 31;
    const int g = blockIdx.x * 4 + w;     // 512 half-chains
    const int b = g >> 1;
    const bool fwd = (g & 1) == 0;

    // --- Load E into registers (one-time) ---
    u64 Er[NK];
    if (fwd) {
        // Er[i] = (exp(T[i][2l]), exp(T[i][2l+1]))   (column pair 2l,2l+1)
        #pragma unroll
        for (int i = 0; i < NK; i++) {
            float2 tv = ((const float2*)(trans + i * NK))[l];
            Er[i] = pack2(expf(tv.x), expf(tv.y));
        }
    } else {
        // Er[j] = (exp(T[2l][j]), exp(T[2l+1][j]))   (row pair 2l,2l+1)
        #pragma unroll
        for (int j = 0; j < NK; j++) {
            Er[j] = pack2(expf(trans[(2 * l) * NK + j]),
                          expf(trans[(2 * l + 1) * NK + j]));
        }
    }

    const float2* sp = (const float2*)(scores + (size_t)b * NS * NK) + l; // row r -> sp[r*32]
    float off = 0.f;
    float2 a;

    if (fwd) {
        // alpha_0 = exp(source + scores[b,0,:])
        float2 s0 = sp[0];
        a.x = expf(source[2 * l] + s0.x);
        a.y = expf(source[2 * l + 1] + s0.y);
        sh[w][0][2 * l]     = pack2(a.x, a.x);
        sh[w][0][2 * l + 1] = pack2(a.y, a.y);
        __syncwarp();

        float2 buf[4];
        #pragma unroll
        for (int i = 0; i < 4; i++) buf[i] = sp[(1 + i) * 32];

        #pragma unroll 4
        for (int t = 1; t <= 1023; t++) {
            // matvec: z[j] = sum_i a[i] * E[i][j]
            const ulonglong2* q = (const ulonglong2*)sh[w][(t - 1) & 1];
            u64 c0 = 0, c1 = 0, c2 = 0, c3 = 0;
            #pragma unroll
            for (int gg = 0; gg < 16; gg++) {
                ulonglong2 p0 = q[2 * gg];
                ulonglong2 p1 = q[2 * gg + 1];
                c0 = fma2(p0.x, Er[4 * gg],     c0);
                c1 = fma2(p0.y, Er[4 * gg + 1], c1);
                c2 = fma2(p1.x, Er[4 * gg + 2], c2);
                c3 = fma2(p1.y, Er[4 * gg + 3], c3);
            }
            float2 z = unpack2(add2(add2(c0, c1), add2(c2, c3)));

            float2 sv = buf[(t - 1) & 3];
            if (t + 4 <= 1023) buf[(t - 1) & 3] = sp[(t + 4) * 32];

            a.x = z.x * __expf(sv.x);
            a.y = z.y * __expf(sv.y);

            if ((t & 3) == 0) {  // exact power-of-two rescale
                float m = fmaxf(a.x, a.y);
                #pragma unroll
                for (int d = 16; d; d >>= 1) m = fmaxf(m, __shfl_xor_sync(0xffffffffu, m, d));
                int k = (__float_as_int(m) >> 23) - 127;
                float sc = __int_as_float((127 - k) << 23);   // 2^-k
                a.x *= sc; a.y *= sc;
                off += (float)k * 0.69314718055994531f;
            }

            sh[w][t & 1][2 * l]     = pack2(a.x, a.x);
            sh[w][t & 1][2 * l + 1] = pack2(a.y, a.y);
            __syncwarp();
        }
        g_vecA[b][2 * l] = a.x;
        g_vecA[b][2 * l + 1] = a.y;
        if (l == 0) g_offA[b] = off;
    } else {
        // beta_{2047} = exp(sink); beta_t[i] = sum_j E[i][j]*exp(s_{t+1}[j])*beta_{t+1}[j]
        a.x = expf(sink[2 * l]);
        a.y = expf(sink[2 * l + 1]);

        float2 buf[4];
        #pragma unroll
        for (int i = 0; i < 4; i++) buf[i] = sp[(2047 - i) * 32];

        #pragma unroll 4
        for (int n = 0; n < 1024; n++) {   // processing score row r = 2047 - n
            float2 sv = buf[n & 3];
            if (n + 4 < 1024) buf[n & 3] = sp[(2047 - (n + 4)) * 32];

            float2 w2;
            w2.x = a.x * __expf(sv.x);
            w2.y = a.y * __expf(sv.y);

            if ((n & 3) == 3) {
                float m = fmaxf(w2.x, w2.y);
                #pragma unroll
                for (int d = 16; d; d >>= 1) m = fmaxf(m, __shfl_xor_sync(0xffffffffu, m, d));
                int k = (__float_as_int(m) >> 23) - 127;
                float sc = __int_as_float((127 - k) << 23);
                w2.x *= sc; w2.y *= sc;
                off += (float)k * 0.69314718055994531f;
            }

            sh[w][n & 1][2 * l]     = pack2(w2.x, w2.x);
            sh[w][n & 1][2 * l + 1] = pack2(w2.y, w2.y);
            __syncwarp();

            // matvec: beta_new[i] = sum_j E[i][j] * w[j]   (Er holds row pairs)
            const ulonglong2* q = (const ulonglong2*)sh[w][n & 1];
            u64 c0 = 0, c1 = 0, c2 = 0, c3 = 0;
            #pragma unroll
            for (int gg = 0; gg < 16; gg++) {
                ulonglong2 p0 = q[2 * gg];
                ulonglong2 p1 = q[2 * gg + 1];
                c0 = fma2(p0.x, Er[4 * gg],     c0);
                c1 = fma2(p0.y, Er[4 * gg + 1], c1);
                c2 = fma2(p1.x, Er[4 * gg + 2], c2);
                c3 = fma2(p1.y, Er[4 * gg + 3], c3);
            }
            a = unpack2(add2(add2(c0, c1), add2(c2, c3)));
            __syncwarp();
        }
        g_vecB[b][2 * l] = a.x;
        g_vecB[b][2 * l + 1] = a.y;
        if (l == 0) g_offB[b] = off;
    }
}

// Gold path score: source[st0] + sum_t scores[b,t,st_t] + sum_t T[st_t,st_{t+1}] + sink[st_last]
__global__ void crf_gold(const float* __restrict__ scores, const int* __restrict__ states,
                         const float* __restrict__ trans, const float* __restrict__ source,
                         const float* __restrict__ sink)
{
    const int b = blockIdx.x;
    const int* st = states + b * NS;
    const float* sc = scores + (size_t)b * NS * NK;

    float acc = 0.f;
    for (int t = threadIdx.x; t < NS; t += blockDim.x) {
        int s = st[t];
        acc += sc[t * NK + s];
        if (t + 1 < NS) acc += trans[s * NK + st[t + 1]];
    }
    if (threadIdx.x == 0) acc += source[st[0]] + sink[st[NS - 1]];

    __shared__ float red[256];
    red[threadIdx.x] = acc;
    __syncthreads();
    #pragma unroll
    for (int s2 = 128; s2; s2 >>= 1) {
        if (threadIdx.x < s2) red[threadIdx.x] += red[threadIdx.x + s2];
        __syncthreads();
    }
    if (threadIdx.x == 0) g_gold[b] = red[0];
}

// logZ_b = log(sum_j A[b][j]*B[b][j]) + offA + offB ; loss mean over batch
__global__ void crf_combine(float* __restrict__ out)
{
    const int b = threadIdx.x;   // 256 threads
    float s = 0.f;
    #pragma unroll
    for (int j = 0; j < NK; j++) s += g_vecA[b][j] * g_vecB[b][j];
    float loss = logf(s) + g_offA[b] + g_offB[b] - g_gold[b];

    __shared__ float red[256];
    red[b] = loss;
    __syncthreads();
    #pragma unroll
    for (int k = 128; k; k >>= 1) {
        if (b < k) red[b] += red[b + k];
        __syncthreads();
    }
    if (b == 0) out[0] = red[0] * (1.0f / NB);
}

extern "C" void kernel_launch(void* const* d_in, const int* in_sizes, int n_in,
                              void* d_out, int out_size)
{
    const float* scores = (const float*)d_in[0];
    const int*   states = (const int*)d_in[1];
    const float* trans  = (const float*)d_in[2];
    const float* source = (const float*)d_in[3];
    const float* sink   = (const float*)d_in[4];

    crf_gold<<<NB, 256>>>(scores, states, trans, source, sink);
    crf_chains<<<128, 128>>>(scores, trans, source, sink);
    crf_combine<<<1, 256>>>((float*)d_out);
}